// round 5
// baseline (speedup 1.0000x reference)
#include <cuda_runtime.h>
#include <cuda_fp16.h>

#define N_NODES_MAX 50000
#define N_EDGES_MAX 800000
#define D 64
#define SCAN_B 1024

// Scratch (no cudaMalloc allowed)
__device__ float  g_agg[N_NODES_MAX * D];
__device__ __half g_h1 [N_NODES_MAX * D];     // layer-1 output, fp16
__device__ __half g_vh [N_NODES_MAX * D];     // input v converted to fp16
__device__ int    g_ibuf[N_NODES_MAX + 64];   // [0,n): deg | [n, n+64): chain
__device__ int    g_off [N_NODES_MAX + 1];
__device__ int    g_cur [N_NODES_MAX];
__device__ int    g_eidx[N_EDGES_MAX];

// ---------------------------------------------------------------------------
// Fused: v -> fp16 conversion (first conv_blocks) + dst histogram (rest)
// ---------------------------------------------------------------------------
__global__ void hist_conv_kernel(const int* __restrict__ dst,
                                 int* __restrict__ deg, int n_edges,
                                 const float4* __restrict__ v4,
                                 uint2* __restrict__ vh, int nconv,
                                 int conv_blocks) {
    int tid = threadIdx.x;
    if ((int)blockIdx.x < conv_blocks) {
        int j = blockIdx.x * 256 + tid;
        if (j < nconv) {
            float4 a = v4[j];
            uint2 o;
            __half2 p0 = __floats2half2_rn(a.x, a.y);
            __half2 p1 = __floats2half2_rn(a.z, a.w);
            o.x = *(unsigned*)&p0;
            o.y = *(unsigned*)&p1;
            vh[j] = o;
        }
    } else {
        int i = (blockIdx.x - conv_blocks) * 256 + tid;
        if (i < n_edges) atomicAdd(deg + __ldg(dst + i), 1);
    }
}

// ---------------------------------------------------------------------------
// Single-pass scan: per-block shuffle scan + chained cross-block prefix.
// Publish/poll via L2 atomics (coherent). Bounded poll: if the predecessor
// never publishes (co-residency assumption broken), fall back to a direct
// coalesced sum of deg[0 .. bid*SCAN_B) — slow but guaranteed to terminate.
// chain[] must be zeroed before launch; published value = inclusive+1.
// ---------------------------------------------------------------------------
__global__ __launch_bounds__(SCAN_B) void scan_kernel(
    const int* __restrict__ deg, int* __restrict__ chain,
    int* __restrict__ off, int* __restrict__ cur, int n) {
    __shared__ int wsum[32];
    __shared__ int sprefix;
    int tid = threadIdx.x;
    int bid = blockIdx.x;
    int lane = tid & 31, w = tid >> 5;
    int i = bid * SCAN_B + tid;
    int v = (i < n) ? deg[i] : 0;

    // warp inclusive scan
    int x = v;
    #pragma unroll
    for (int o = 1; o < 32; o <<= 1) {
        int t = __shfl_up_sync(0xffffffffu, x, o);
        if (lane >= o) x += t;
    }
    if (lane == 31) wsum[w] = x;
    __syncthreads();
    if (w == 0) {
        int y = wsum[lane];
        #pragma unroll
        for (int o = 1; o < 32; o <<= 1) {
            int t = __shfl_up_sync(0xffffffffu, y, o);
            if (lane >= o) y += t;
        }
        wsum[lane] = y;
    }
    __syncthreads();
    int incl = x + ((w > 0) ? wsum[w - 1] : 0);
    int aggregate = wsum[31];

    if (tid == 0) sprefix = -1;
    __syncthreads();

    if (tid == 0 && bid > 0) {
        int t = 0;
        long long tries = 0;
        while ((t = atomicAdd(chain + bid - 1, 0)) == 0) {
            __nanosleep(20);
            if (++tries > 1000000) break;   // fallback path below
        }
        if (t != 0) sprefix = t - 1;
    } else if (tid == 0) {
        sprefix = 0;
    }
    __syncthreads();

    if (sprefix < 0) {
        // Fallback: direct block-wide coalesced sum of deg[0 .. bid*SCAN_B)
        int lim = bid * SCAN_B;
        int s = 0;
        for (int j = tid; j < lim; j += SCAN_B) s += deg[j];
        #pragma unroll
        for (int o = 16; o > 0; o >>= 1)
            s += __shfl_down_sync(0xffffffffu, s, o);
        if (lane == 0) wsum[w] = s;
        __syncthreads();
        if (tid == 0) {
            int tot = 0;
            #pragma unroll
            for (int q = 0; q < 32; q++) tot += wsum[q];
            sprefix = tot;
        }
        __syncthreads();
    }

    if (tid == 0) atomicExch(chain + bid, sprefix + aggregate + 1);

    int ex = sprefix + incl - v;
    if (i < n) { off[i] = ex; cur[i] = ex; }
    if (i == n - 1) off[n] = ex + v;
}

// ---------------------------------------------------------------------------
// CSR fill: claim slot per edge, record src node
// ---------------------------------------------------------------------------
__global__ void fill_kernel(const int* __restrict__ src,
                            const int* __restrict__ dst,
                            int* __restrict__ cur, int* __restrict__ eidx,
                            int n_edges) {
    int i = blockIdx.x * blockDim.x + threadIdx.x;
    if (i < n_edges) {
        int p = atomicAdd(cur + __ldg(dst + i), 1);
        eidx[p] = __ldg(src + i);
    }
}

// ---------------------------------------------------------------------------
// Gather (fp16 payload, fp32 accumulate): agg[n] = sum h[src].
// One warp per node; half-warp per edge (16 lanes x uint2 = 64 halves).
// ---------------------------------------------------------------------------
__global__ __launch_bounds__(256) void gather_kernel(
    const uint2* __restrict__ hv, const int* __restrict__ eidx,
    const int* __restrict__ off, float* __restrict__ agg, int n) {
    int warp = (blockIdx.x * blockDim.x + threadIdx.x) >> 5;
    if (warp >= n) return;
    int lane = threadIdx.x & 31;
    int half = lane >> 4;
    int hl   = lane & 15;
    int o    = __ldg(off + warp);
    int e    = __ldg(off + warp + 1);

    float4 acc = make_float4(0.f, 0.f, 0.f, 0.f);
    int i = o + half;
    for (; i + 6 < e; i += 8) {
        int s0 = __ldg(eidx + i);
        int s1 = __ldg(eidx + i + 2);
        int s2 = __ldg(eidx + i + 4);
        int s3 = __ldg(eidx + i + 6);
        uint2 u0 = hv[s0 * 16 + hl];
        uint2 u1 = hv[s1 * 16 + hl];
        uint2 u2 = hv[s2 * 16 + hl];
        uint2 u3 = hv[s3 * 16 + hl];
        float2 a0 = __half22float2(*(__half2*)&u0.x), b0 = __half22float2(*(__half2*)&u0.y);
        float2 a1 = __half22float2(*(__half2*)&u1.x), b1 = __half22float2(*(__half2*)&u1.y);
        float2 a2 = __half22float2(*(__half2*)&u2.x), b2 = __half22float2(*(__half2*)&u2.y);
        float2 a3 = __half22float2(*(__half2*)&u3.x), b3 = __half22float2(*(__half2*)&u3.y);
        acc.x += a0.x + a1.x + a2.x + a3.x;
        acc.y += a0.y + a1.y + a2.y + a3.y;
        acc.z += b0.x + b1.x + b2.x + b3.x;
        acc.w += b0.y + b1.y + b2.y + b3.y;
    }
    for (; i < e; i += 2) {
        int s = __ldg(eidx + i);
        uint2 u = hv[s * 16 + hl];
        float2 a = __half22float2(*(__half2*)&u.x), b = __half22float2(*(__half2*)&u.y);
        acc.x += a.x; acc.y += a.y; acc.z += b.x; acc.w += b.y;
    }
    acc.x += __shfl_down_sync(0xffffffffu, acc.x, 16);
    acc.y += __shfl_down_sync(0xffffffffu, acc.y, 16);
    acc.z += __shfl_down_sync(0xffffffffu, acc.z, 16);
    acc.w += __shfl_down_sync(0xffffffffu, acc.w, 16);
    if (half == 0)
        *reinterpret_cast<float4*>(agg + (size_t)warp * D + hl * 4) = acc;
}

// ---------------------------------------------------------------------------
// Y(fp16) = relu(X @ W + b). Thread-per-row, W broadcast from smem.
// ---------------------------------------------------------------------------
__global__ __launch_bounds__(256) void gemm_relu_h_kernel(
    const float* __restrict__ X, const float* __restrict__ W,
    const float* __restrict__ b, uint2* __restrict__ Yh, int n) {
    __shared__ float4 Ws[D * 16];
    __shared__ float  bs[D];
    int tid = threadIdx.x;
    for (int i = tid; i < D * 16; i += 256) Ws[i] = reinterpret_cast<const float4*>(W)[i];
    if (tid < D) bs[tid] = b[tid];
    __syncthreads();

    int row = blockIdx.x * 256 + tid;
    if (row >= n) return;
    const float4* xr = reinterpret_cast<const float4*>(X + (size_t)row * D);

    float4 acc[16];
    #pragma unroll
    for (int j = 0; j < 16; j++) acc[j] = reinterpret_cast<const float4*>(bs)[j];

    #pragma unroll 4
    for (int kc = 0; kc < 16; kc++) {
        float4 x = xr[kc];
        int kb = kc * 4;
        #pragma unroll
        for (int j = 0; j < 16; j++) {
            float4 a = acc[j];
            float4 w;
            w = Ws[(kb + 0) * 16 + j];
            a.x += x.x * w.x; a.y += x.x * w.y; a.z += x.x * w.z; a.w += x.x * w.w;
            w = Ws[(kb + 1) * 16 + j];
            a.x += x.y * w.x; a.y += x.y * w.y; a.z += x.y * w.z; a.w += x.y * w.w;
            w = Ws[(kb + 2) * 16 + j];
            a.x += x.z * w.x; a.y += x.z * w.y; a.z += x.z * w.z; a.w += x.z * w.w;
            w = Ws[(kb + 3) * 16 + j];
            a.x += x.w * w.x; a.y += x.w * w.y; a.z += x.w * w.z; a.w += x.w * w.w;
            acc[j] = a;
        }
    }

    uint2* yr = Yh + (size_t)row * 16;
    #pragma unroll
    for (int j = 0; j < 16; j++) {
        float4 a = acc[j];
        __half2 p0 = __floats2half2_rn(fmaxf(a.x, 0.f), fmaxf(a.y, 0.f));
        __half2 p1 = __floats2half2_rn(fmaxf(a.z, 0.f), fmaxf(a.w, 0.f));
        uint2 o;
        o.x = *(unsigned*)&p0;
        o.y = *(unsigned*)&p1;
        yr[j] = o;
    }
}

// ---------------------------------------------------------------------------
// Layer-2 GEMM + relu + both heads fused (fp32 in, fp32 out).
// ---------------------------------------------------------------------------
__global__ __launch_bounds__(256) void gemm_heads_kernel(
    const float* __restrict__ X, const float* __restrict__ W,
    const float* __restrict__ b,
    const float* __restrict__ Wa, const float* __restrict__ ba,
    const float* __restrict__ Wb, const float* __restrict__ bb,
    float* __restrict__ xa_out, float* __restrict__ xb_out, int n) {
    __shared__ float4 Ws[D * 16];
    __shared__ float  bs[D];
    __shared__ float  Was[D * 2];
    __shared__ float  Wbs[D * 16];
    __shared__ float  bas[2];
    __shared__ float  bbs[16];
    int tid = threadIdx.x;
    for (int i = tid; i < D * 16; i += 256) Ws[i] = reinterpret_cast<const float4*>(W)[i];
    for (int i = tid; i < D * 16; i += 256) Wbs[i] = Wb[i];
    if (tid < D * 2) Was[tid] = Wa[tid];
    if (tid < D) bs[tid] = b[tid];
    if (tid < 2) bas[tid] = ba[tid];
    if (tid < 16) bbs[tid] = bb[tid];
    __syncthreads();

    int row = blockIdx.x * 256 + tid;
    if (row >= n) return;
    const float4* xr = reinterpret_cast<const float4*>(X + (size_t)row * D);

    float4 acc[16];
    #pragma unroll
    for (int j = 0; j < 16; j++) acc[j] = reinterpret_cast<const float4*>(bs)[j];

    #pragma unroll 4
    for (int kc = 0; kc < 16; kc++) {
        float4 x = xr[kc];
        int kb = kc * 4;
        #pragma unroll
        for (int j = 0; j < 16; j++) {
            float4 a = acc[j];
            float4 w;
            w = Ws[(kb + 0) * 16 + j];
            a.x += x.x * w.x; a.y += x.x * w.y; a.z += x.x * w.z; a.w += x.x * w.w;
            w = Ws[(kb + 1) * 16 + j];
            a.x += x.y * w.x; a.y += x.y * w.y; a.z += x.y * w.z; a.w += x.y * w.w;
            w = Ws[(kb + 2) * 16 + j];
            a.x += x.z * w.x; a.y += x.z * w.y; a.z += x.z * w.z; a.w += x.z * w.w;
            w = Ws[(kb + 3) * 16 + j];
            a.x += x.w * w.x; a.y += x.w * w.y; a.z += x.w * w.z; a.w += x.w * w.w;
            acc[j] = a;
        }
    }

    float h[D];
    #pragma unroll
    for (int j = 0; j < 16; j++) {
        h[4*j+0] = fmaxf(acc[j].x, 0.f);
        h[4*j+1] = fmaxf(acc[j].y, 0.f);
        h[4*j+2] = fmaxf(acc[j].z, 0.f);
        h[4*j+3] = fmaxf(acc[j].w, 0.f);
    }

    float a0 = bas[0], a1 = bas[1];
    #pragma unroll
    for (int j = 0; j < D; j++) {
        a0 += h[j] * Was[j * 2 + 0];
        a1 += h[j] * Was[j * 2 + 1];
    }
    xa_out[(size_t)row * 2 + 0] = a0;
    xa_out[(size_t)row * 2 + 1] = a1;

    float hb[16];
    #pragma unroll
    for (int t = 0; t < 16; t++) hb[t] = bbs[t];
    #pragma unroll
    for (int j = 0; j < D; j++) {
        float hv = h[j];
        #pragma unroll
        for (int t = 0; t < 16; t++) hb[t] += hv * Wbs[j * 16 + t];
    }
    float4* out4 = reinterpret_cast<float4*>(xb_out + (size_t)row * 16);
    #pragma unroll
    for (int q = 0; q < 4; q++)
        out4[q] = make_float4(hb[4*q+0], hb[4*q+1], hb[4*q+2], hb[4*q+3]);
}

// ---------------------------------------------------------------------------
extern "C" void kernel_launch(void* const* d_in, const int* in_sizes, int n_in,
                              void* d_out, int out_size) {
    const float* v   = (const float*)d_in[0];
    const int*   src = (const int*)  d_in[1];
    const int*   dst = (const int*)  d_in[2];
    const float* W1  = (const float*)d_in[3];
    const float* b1  = (const float*)d_in[4];
    const float* W2  = (const float*)d_in[5];
    const float* b2  = (const float*)d_in[6];
    const float* Wa  = (const float*)d_in[7];
    const float* ba  = (const float*)d_in[8];
    const float* Wb  = (const float*)d_in[9];
    const float* bb  = (const float*)d_in[10];

    int n_nodes = in_sizes[0] / D;
    int n_edges = in_sizes[1];

    float*  agg;  cudaGetSymbolAddress((void**)&agg,  g_agg);
    __half* h1;   cudaGetSymbolAddress((void**)&h1,   g_h1);
    __half* vh;   cudaGetSymbolAddress((void**)&vh,   g_vh);
    int*    ibuf; cudaGetSymbolAddress((void**)&ibuf, g_ibuf);
    int*    off;  cudaGetSymbolAddress((void**)&off,  g_off);
    int*    cur;  cudaGetSymbolAddress((void**)&cur,  g_cur);
    int*    eidx; cudaGetSymbolAddress((void**)&eidx, g_eidx);

    int* deg   = ibuf;
    int* chain = ibuf + n_nodes;

    float* xa_out = (float*)d_out;
    float* xb_out = (float*)d_out + (size_t)n_nodes * 2;

    int nconv = n_nodes * D / 4;
    int conv_blocks   = (nconv + 255) / 256;
    int edge_blocks   = (n_edges + 255) / 256;
    int scan_blocks   = (n_nodes + SCAN_B - 1) / SCAN_B;
    int gather_blocks = (n_nodes * 32 + 255) / 256;
    int gemm_blocks   = (n_nodes + 255) / 256;

    // ---- CSR build + fp16 conversion ----
    cudaMemsetAsync(ibuf, 0, (n_nodes + 64) * sizeof(int));
    hist_conv_kernel<<<conv_blocks + edge_blocks, 256>>>(
        dst, deg, n_edges, (const float4*)v, (uint2*)vh, nconv, conv_blocks);
    scan_kernel<<<scan_blocks, SCAN_B>>>(deg, chain, off, cur, n_nodes);
    fill_kernel<<<edge_blocks, 256>>>(src, dst, cur, eidx, n_edges);

    // ---- Layer 1 ----
    gather_kernel<<<gather_blocks, 256>>>((const uint2*)vh, eidx, off, agg, n_nodes);
    gemm_relu_h_kernel<<<gemm_blocks, 256>>>(agg, W1, b1, (uint2*)h1, n_nodes);

    // ---- Layer 2 + heads ----
    gather_kernel<<<gather_blocks, 256>>>((const uint2*)h1, eidx, off, agg, n_nodes);
    gemm_heads_kernel<<<gemm_blocks, 256>>>(agg, W2, b2, Wa, ba, Wb, bb,
                                            xa_out, xb_out, n_nodes);
}

// round 7
// speedup vs baseline: 1.2833x; 1.2833x over previous
#include <cuda_runtime.h>
#include <cuda_bf16.h>

#define N_NODES_MAX 50000
#define N_EDGES_MAX 800000
#define D 64
#define SCAN_B 1024
#define MAX_SBLK ((N_NODES_MAX + SCAN_B - 1) / SCAN_B)   // 49

// Scratch (no cudaMalloc allowed)
__device__ float g_agg [N_NODES_MAX * D];
__device__ float g_h1  [N_NODES_MAX * D];
__device__ int   g_deg [N_NODES_MAX];
__device__ int   g_off [N_NODES_MAX + 1];
__device__ int   g_cur [N_NODES_MAX];
__device__ int   g_eidx[N_EDGES_MAX];
__device__ int   g_bsum[MAX_SBLK + 1];

// ---------------------------------------------------------------------------
// CSR step 1: histogram of dst (one thread per edge)
// ---------------------------------------------------------------------------
__global__ void hist_kernel(const int* __restrict__ dst, int* __restrict__ deg,
                            int n_edges) {
    int i = blockIdx.x * blockDim.x + threadIdx.x;
    if (i < n_edges) atomicAdd(deg + __ldg(dst + i), 1);
}

// ---------------------------------------------------------------------------
// CSR step 2a: per-block sums of deg (coalesced)
// ---------------------------------------------------------------------------
__global__ __launch_bounds__(SCAN_B) void scanA_kernel(
    const int* __restrict__ deg, int* __restrict__ bsum, int n) {
    __shared__ int s[SCAN_B];
    int tid = threadIdx.x;
    int i = blockIdx.x * SCAN_B + tid;
    s[tid] = (i < n) ? deg[i] : 0;
    __syncthreads();
    #pragma unroll
    for (int o = SCAN_B / 2; o > 0; o >>= 1) {
        if (tid < o) s[tid] += s[tid + o];
        __syncthreads();
    }
    if (tid == 0) bsum[blockIdx.x] = s[0];
}

// ---------------------------------------------------------------------------
// CSR step 2b: exclusive scan of block sums (tiny, one block)
// ---------------------------------------------------------------------------
__global__ __launch_bounds__(64) void scanB_kernel(int* __restrict__ bsum, int nb) {
    __shared__ int s[64];
    int tid = threadIdx.x;
    int v = (tid < nb) ? bsum[tid] : 0;
    s[tid] = v;
    __syncthreads();
    #pragma unroll
    for (int o = 1; o < 64; o <<= 1) {
        int t = (tid >= o) ? s[tid - o] : 0;
        __syncthreads();
        s[tid] += t;
        __syncthreads();
    }
    if (tid < nb) bsum[tid] = s[tid] - v;   // exclusive
}

// ---------------------------------------------------------------------------
// CSR step 2c: per-element offsets = block base + in-block exclusive scan
// ---------------------------------------------------------------------------
__global__ __launch_bounds__(SCAN_B) void scanC_kernel(
    const int* __restrict__ deg, const int* __restrict__ bsum,
    int* __restrict__ off, int* __restrict__ cur, int n) {
    __shared__ int s[SCAN_B];
    int tid = threadIdx.x;
    int i = blockIdx.x * SCAN_B + tid;
    int v = (i < n) ? deg[i] : 0;
    s[tid] = v;
    __syncthreads();
    #pragma unroll
    for (int o = 1; o < SCAN_B; o <<= 1) {
        int t = (tid >= o) ? s[tid - o] : 0;
        __syncthreads();
        s[tid] += t;
        __syncthreads();
    }
    int ex = bsum[blockIdx.x] + s[tid] - v;
    if (i < n) { off[i] = ex; cur[i] = ex; }
    if (i == n - 1) off[n] = ex + v;
}

// ---------------------------------------------------------------------------
// CSR step 3: fill — claim slot per edge, record src node
// ---------------------------------------------------------------------------
__global__ void fill_kernel(const int* __restrict__ src,
                            const int* __restrict__ dst,
                            int* __restrict__ cur, int* __restrict__ eidx,
                            int n_edges) {
    int i = blockIdx.x * blockDim.x + threadIdx.x;
    if (i < n_edges) {
        int p = atomicAdd(cur + __ldg(dst + i), 1);
        eidx[p] = __ldg(src + i);
    }
}

// ---------------------------------------------------------------------------
// Gather: agg[n] = sum over incoming edges of h[src].
// One warp per node; half-warp per edge (16 lanes x float4).
// Fully predicated: EVERY iteration keeps 4 loads in flight (out-of-range
// slots clamp their index into [o, e) and contribute weight 0 via FFMA).
// ---------------------------------------------------------------------------
__global__ __launch_bounds__(256) void gather_kernel(
    const float* __restrict__ h, const int* __restrict__ eidx,
    const int* __restrict__ off, float* __restrict__ agg, int n) {
    int warp = (blockIdx.x * blockDim.x + threadIdx.x) >> 5;
    if (warp >= n) return;
    int lane = threadIdx.x & 31;
    int half = lane >> 4;
    int hl   = lane & 15;
    int o    = __ldg(off + warp);
    int e    = __ldg(off + warp + 1);
    int last = max(o, e - 1);   // provably in [o, e) whenever the loop runs

    float4 acc = make_float4(0.f, 0.f, 0.f, 0.f);
    for (int i = o + half; i < e; i += 8) {
        int j1 = i + 2, j2 = i + 4, j3 = i + 6;
        int s0 = __ldg(eidx + i);
        int s1 = __ldg(eidx + min(j1, last));
        int s2 = __ldg(eidx + min(j2, last));
        int s3 = __ldg(eidx + min(j3, last));
        float m1 = (j1 < e) ? 1.f : 0.f;
        float m2 = (j2 < e) ? 1.f : 0.f;
        float m3 = (j3 < e) ? 1.f : 0.f;
        float4 v0 = *reinterpret_cast<const float4*>(h + (size_t)s0 * D + hl * 4);
        float4 v1 = *reinterpret_cast<const float4*>(h + (size_t)s1 * D + hl * 4);
        float4 v2 = *reinterpret_cast<const float4*>(h + (size_t)s2 * D + hl * 4);
        float4 v3 = *reinterpret_cast<const float4*>(h + (size_t)s3 * D + hl * 4);
        acc.x += v0.x + m1 * v1.x + m2 * v2.x + m3 * v3.x;
        acc.y += v0.y + m1 * v1.y + m2 * v2.y + m3 * v3.y;
        acc.z += v0.z + m1 * v1.z + m2 * v2.z + m3 * v3.z;
        acc.w += v0.w + m1 * v1.w + m2 * v2.w + m3 * v3.w;
    }
    acc.x += __shfl_down_sync(0xffffffffu, acc.x, 16);
    acc.y += __shfl_down_sync(0xffffffffu, acc.y, 16);
    acc.z += __shfl_down_sync(0xffffffffu, acc.z, 16);
    acc.w += __shfl_down_sync(0xffffffffu, acc.w, 16);
    if (half == 0)
        *reinterpret_cast<float4*>(agg + (size_t)warp * D + hl * 4) = acc;
}

// ---------------------------------------------------------------------------
// Y = relu(X @ W + b). Thread-per-row, W broadcast from smem.
// ---------------------------------------------------------------------------
__global__ __launch_bounds__(256) void gemm_relu_kernel(
    const float* __restrict__ X, const float* __restrict__ W,
    const float* __restrict__ b, float* __restrict__ Y, int n) {
    __shared__ float4 Ws[D * 16];
    __shared__ float  bs[D];
    int tid = threadIdx.x;
    for (int i = tid; i < D * 16; i += 256) Ws[i] = reinterpret_cast<const float4*>(W)[i];
    if (tid < D) bs[tid] = b[tid];
    __syncthreads();

    int row = blockIdx.x * 256 + tid;
    if (row >= n) return;
    const float4* xr = reinterpret_cast<const float4*>(X + (size_t)row * D);

    float4 acc[16];
    #pragma unroll
    for (int j = 0; j < 16; j++) acc[j] = reinterpret_cast<const float4*>(bs)[j];

    #pragma unroll 4
    for (int kc = 0; kc < 16; kc++) {
        float4 x = xr[kc];
        int kb = kc * 4;
        #pragma unroll
        for (int j = 0; j < 16; j++) {
            float4 a = acc[j];
            float4 w;
            w = Ws[(kb + 0) * 16 + j];
            a.x += x.x * w.x; a.y += x.x * w.y; a.z += x.x * w.z; a.w += x.x * w.w;
            w = Ws[(kb + 1) * 16 + j];
            a.x += x.y * w.x; a.y += x.y * w.y; a.z += x.y * w.z; a.w += x.y * w.w;
            w = Ws[(kb + 2) * 16 + j];
            a.x += x.z * w.x; a.y += x.z * w.y; a.z += x.z * w.z; a.w += x.z * w.w;
            w = Ws[(kb + 3) * 16 + j];
            a.x += x.w * w.x; a.y += x.w * w.y; a.z += x.w * w.z; a.w += x.w * w.w;
            acc[j] = a;
        }
    }

    float4* yr = reinterpret_cast<float4*>(Y + (size_t)row * D);
    #pragma unroll
    for (int j = 0; j < 16; j++) {
        float4 a = acc[j];
        a.x = fmaxf(a.x, 0.f); a.y = fmaxf(a.y, 0.f);
        a.z = fmaxf(a.z, 0.f); a.w = fmaxf(a.w, 0.f);
        yr[j] = a;
    }
}

// ---------------------------------------------------------------------------
// Layer-2 GEMM + relu + both heads fused.
// ---------------------------------------------------------------------------
__global__ __launch_bounds__(256) void gemm_heads_kernel(
    const float* __restrict__ X, const float* __restrict__ W,
    const float* __restrict__ b,
    const float* __restrict__ Wa, const float* __restrict__ ba,
    const float* __restrict__ Wb, const float* __restrict__ bb,
    float* __restrict__ xa_out, float* __restrict__ xb_out, int n) {
    __shared__ float4 Ws[D * 16];
    __shared__ float  bs[D];
    __shared__ float  Was[D * 2];
    __shared__ float  Wbs[D * 16];
    __shared__ float  bas[2];
    __shared__ float  bbs[16];
    int tid = threadIdx.x;
    for (int i = tid; i < D * 16; i += 256) Ws[i] = reinterpret_cast<const float4*>(W)[i];
    for (int i = tid; i < D * 16; i += 256) Wbs[i] = Wb[i];
    if (tid < D * 2) Was[tid] = Wa[tid];
    if (tid < D) bs[tid] = b[tid];
    if (tid < 2) bas[tid] = ba[tid];
    if (tid < 16) bbs[tid] = bb[tid];
    __syncthreads();

    int row = blockIdx.x * 256 + tid;
    if (row >= n) return;
    const float4* xr = reinterpret_cast<const float4*>(X + (size_t)row * D);

    float4 acc[16];
    #pragma unroll
    for (int j = 0; j < 16; j++) acc[j] = reinterpret_cast<const float4*>(bs)[j];

    #pragma unroll 4
    for (int kc = 0; kc < 16; kc++) {
        float4 x = xr[kc];
        int kb = kc * 4;
        #pragma unroll
        for (int j = 0; j < 16; j++) {
            float4 a = acc[j];
            float4 w;
            w = Ws[(kb + 0) * 16 + j];
            a.x += x.x * w.x; a.y += x.x * w.y; a.z += x.x * w.z; a.w += x.x * w.w;
            w = Ws[(kb + 1) * 16 + j];
            a.x += x.y * w.x; a.y += x.y * w.y; a.z += x.y * w.z; a.w += x.y * w.w;
            w = Ws[(kb + 2) * 16 + j];
            a.x += x.z * w.x; a.y += x.z * w.y; a.z += x.z * w.z; a.w += x.z * w.w;
            w = Ws[(kb + 3) * 16 + j];
            a.x += x.w * w.x; a.y += x.w * w.y; a.z += x.w * w.z; a.w += x.w * w.w;
            acc[j] = a;
        }
    }

    float h[D];
    #pragma unroll
    for (int j = 0; j < 16; j++) {
        h[4*j+0] = fmaxf(acc[j].x, 0.f);
        h[4*j+1] = fmaxf(acc[j].y, 0.f);
        h[4*j+2] = fmaxf(acc[j].z, 0.f);
        h[4*j+3] = fmaxf(acc[j].w, 0.f);
    }

    float a0 = bas[0], a1 = bas[1];
    #pragma unroll
    for (int j = 0; j < D; j++) {
        a0 += h[j] * Was[j * 2 + 0];
        a1 += h[j] * Was[j * 2 + 1];
    }
    xa_out[(size_t)row * 2 + 0] = a0;
    xa_out[(size_t)row * 2 + 1] = a1;

    float hb[16];
    #pragma unroll
    for (int t = 0; t < 16; t++) hb[t] = bbs[t];
    #pragma unroll
    for (int j = 0; j < D; j++) {
        float hv = h[j];
        #pragma unroll
        for (int t = 0; t < 16; t++) hb[t] += hv * Wbs[j * 16 + t];
    }
    float4* out4 = reinterpret_cast<float4*>(xb_out + (size_t)row * 16);
    #pragma unroll
    for (int q = 0; q < 4; q++)
        out4[q] = make_float4(hb[4*q+0], hb[4*q+1], hb[4*q+2], hb[4*q+3]);
}

// ---------------------------------------------------------------------------
extern "C" void kernel_launch(void* const* d_in, const int* in_sizes, int n_in,
                              void* d_out, int out_size) {
    const float* v   = (const float*)d_in[0];
    const int*   src = (const int*)  d_in[1];
    const int*   dst = (const int*)  d_in[2];
    const float* W1  = (const float*)d_in[3];
    const float* b1  = (const float*)d_in[4];
    const float* W2  = (const float*)d_in[5];
    const float* b2  = (const float*)d_in[6];
    const float* Wa  = (const float*)d_in[7];
    const float* ba  = (const float*)d_in[8];
    const float* Wb  = (const float*)d_in[9];
    const float* bb  = (const float*)d_in[10];

    int n_nodes = in_sizes[0] / D;
    int n_edges = in_sizes[1];

    float* agg;  cudaGetSymbolAddress((void**)&agg,  g_agg);
    float* h1;   cudaGetSymbolAddress((void**)&h1,   g_h1);
    int*   deg;  cudaGetSymbolAddress((void**)&deg,  g_deg);
    int*   off;  cudaGetSymbolAddress((void**)&off,  g_off);
    int*   cur;  cudaGetSymbolAddress((void**)&cur,  g_cur);
    int*   eidx; cudaGetSymbolAddress((void**)&eidx, g_eidx);
    int*   bsum; cudaGetSymbolAddress((void**)&bsum, g_bsum);

    float* xa_out = (float*)d_out;
    float* xb_out = (float*)d_out + (size_t)n_nodes * 2;

    int edge_blocks   = (n_edges + 255) / 256;
    int scan_blocks   = (n_nodes + SCAN_B - 1) / SCAN_B;
    int gather_blocks = (n_nodes * 32 + 255) / 256;
    int gemm_blocks   = (n_nodes + 255) / 256;

    // ---- CSR build (shared by both layers) ----
    cudaMemsetAsync(deg, 0, n_nodes * sizeof(int));
    hist_kernel <<<edge_blocks, 256>>>(dst, deg, n_edges);
    scanA_kernel<<<scan_blocks, SCAN_B>>>(deg, bsum, n_nodes);
    scanB_kernel<<<1, 64>>>(bsum, scan_blocks);
    scanC_kernel<<<scan_blocks, SCAN_B>>>(deg, bsum, off, cur, n_nodes);
    fill_kernel <<<edge_blocks, 256>>>(src, dst, cur, eidx, n_edges);

    // ---- Layer 1 ----
    gather_kernel<<<gather_blocks, 256>>>(v, eidx, off, agg, n_nodes);
    gemm_relu_kernel<<<gemm_blocks, 256>>>(agg, W1, b1, h1, n_nodes);

    // ---- Layer 2 + heads ----
    gather_kernel<<<gather_blocks, 256>>>(h1, eidx, off, agg, n_nodes);
    gemm_heads_kernel<<<gemm_blocks, 256>>>(agg, W2, b2, Wa, ba, Wb, bb,
                                            xa_out, xb_out, n_nodes);
}